// round 4
// baseline (speedup 1.0000x reference)
#include <cuda_runtime.h>
#include <cstdint>
#include <cmath>

// SA neuron forward scan — time-parallel chunked formulation.
//
// Input : input_current [B=16, T, F=1024] float32 (T=2000 in this problem)
// Output: d_out = concat(imem_trace [B, T+1, F] f32, spikes [B, T+1, F] f32)
//
// While no neuron fires, i_ahp = i_ref = 0 identically and the membrane is a
// linear AR(1):  z' = a*z + c*x,  a = 1 - dt*oma/tau_m = 0.99.
// We exploit that with a 3-phase chunked scan (K chunks of L steps):
//   P1: per (neuron, chunk) partial s_j from z=0     [reads x once]
//   P2: per neuron sequential carry  zc_{j+1} = a^L zc_j + s_j   [tiny]
//   P3: per (neuron, chunk) exact nonlinear replay from zc_j, write outputs,
//       flag any neuron that fires                   [reads x again, writes out]
//   FB: serial exact recompute for flagged neurons (correct for any input;
//       never triggered for this input -> ~2us no-op)

namespace sa {
constexpr double d_TAU_M   = 1e-13 * 0.026 / (0.7 * 2.5e-11);
constexpr double d_DT_S    = (d_TAU_M * 1000.0 / 20.0) * 0.001;
constexpr double d_TAU_AHP = 2.5e-13 * 0.026 / (0.7 * 2e-11);
constexpr double d_TAU_REF = 2e-13 * 0.026 / (0.7 * 1.6e-9);

__device__ __host__ __forceinline__ float f_CUR_SCALE() { return 1e-12f; }
__device__ __host__ __forceinline__ float f_ONE_MINUS_A() { return 0.2f; }
__device__ __host__ __forceinline__ float f_INV_TAU_M() { return (float)(1.0 / d_TAU_M); }
__device__ __host__ __forceinline__ float f_DT_S() { return (float)d_DT_S; }
__device__ __host__ __forceinline__ float f_K_AHP() { return (float)(d_DT_S / d_TAU_AHP); }
__device__ __host__ __forceinline__ float f_K_REF() { return (float)(d_DT_S / d_TAU_REF); }
__device__ __host__ __forceinline__ float f_Z_TH() { return 2.5e-9f; }
__device__ __host__ __forceinline__ float f_R() { return 332.0f; }
__device__ __host__ __forceinline__ float f_I_TH_AHP() { return 1.66e-11f; }
__device__ __host__ __forceinline__ float f_I_REF_ADD() { return 1.6e-9f; }
} // namespace sa

constexpr int B_C = 16;
constexpr int F_C = 1024;
constexpr int N_C = B_C * F_C;          // 16384 neurons
constexpr int L_C = 50;                 // chunk length
constexpr int K_MAX = 128;              // supports T up to 6400

// Scratch (allocation-free rule: __device__ globals)
__device__ float    g_s[K_MAX][N_C];      // chunk partials (zero-carry result)
__device__ float    g_carry[K_MAX][N_C];  // carry-in z per chunk
__device__ unsigned g_flags[N_C];         // per-neuron "fired somewhere" flag

// ---------------------------------------------------------------------------
// P1: chunk partials, pure linear (no-fire) dynamics from z=0
// grid: (N/128, K), block 128. Warp lanes = consecutive f -> coalesced.
// ---------------------------------------------------------------------------
__global__ __launch_bounds__(128)
void sa_p1_partials(const float* __restrict__ in, int T)
{
    const int n = blockIdx.x * blockDim.x + threadIdx.x;
    const int j = blockIdx.y;
    const int t0 = j * L_C;
    if (t0 >= T) return;
    const int b = n >> 10;
    const int f = n & (F_C - 1);
    const float* __restrict__ xp = in + (size_t)b * T * F_C + (size_t)t0 * F_C + f;

    const float cur_scale = sa::f_CUR_SCALE();
    const float oma       = sa::f_ONE_MINUS_A();
    const float inv_tau_m = sa::f_INV_TAU_M();
    const float dt_s      = sa::f_DT_S();

    float z = 0.0f;
    const int cnt = min(L_C, T - t0);
    if (cnt == L_C) {
        #pragma unroll 10
        for (int i = 0; i < L_C; i++) {
            const float x = __ldcs(xp + (size_t)i * F_C);
            const float i_net = x * cur_scale;
            const float dz = fmaf(-oma, z, i_net) * inv_tau_m;
            z = fmaf(dt_s, dz, z);
        }
    } else {
        for (int i = 0; i < cnt; i++) {
            const float x = __ldcs(xp + (size_t)i * F_C);
            const float i_net = x * cur_scale;
            const float dz = fmaf(-oma, z, i_net) * inv_tau_m;
            z = fmaf(dt_s, dz, z);
        }
    }
    g_s[j][n] = z;
}

// ---------------------------------------------------------------------------
// P2: sequential carry combine per neuron, zero flags, imem[:,0,:] = 0
// ---------------------------------------------------------------------------
__global__ __launch_bounds__(128)
void sa_p2_carry(float* __restrict__ imem, int T, int K, float aL, float a1)
{
    const int n = blockIdx.x * blockDim.x + threadIdx.x;
    if (n >= N_C) return;
    g_flags[n] = 0u;

    float zc = 0.0f;
    for (int j = 0; j < K; j++) {
        g_carry[j][n] = zc;
        const int cnt = min(L_C, T - j * L_C);
        const float aj = (cnt == L_C) ? aL : __powf(a1, (float)cnt);
        zc = fmaf(aj, zc, g_s[j][n]);
    }

    // imem_trace[:,0,:] = 0
    const int b = n >> 10;
    const int f = n & (F_C - 1);
    imem[(size_t)b * (T + 1) * F_C + f] = 0.0f;
}

// ---------------------------------------------------------------------------
// P3: exact nonlinear replay per (neuron, chunk) from the linear carry,
//     write imem/spikes, flag any firing neuron.
// ---------------------------------------------------------------------------
__global__ __launch_bounds__(128)
void sa_p3_replay(const float* __restrict__ in,
                  float* __restrict__ imem,
                  float* __restrict__ spk, int T)
{
    const int n = blockIdx.x * blockDim.x + threadIdx.x;
    const int j = blockIdx.y;
    const int t0 = j * L_C;
    if (t0 >= T) return;
    const int b = n >> 10;
    const int f = n & (F_C - 1);

    const float* __restrict__ xp = in + (size_t)b * T * F_C + (size_t)t0 * F_C + f;
    float* __restrict__ ip = imem + (size_t)b * (T + 1) * F_C + (size_t)(t0 + 1) * F_C + f;
    float* __restrict__ sp = spk  + (size_t)b * (T + 1) * F_C + (size_t)t0 * F_C + f;

    const float cur_scale = sa::f_CUR_SCALE();
    const float oma       = sa::f_ONE_MINUS_A();
    const float inv_tau_m = sa::f_INV_TAU_M();
    const float dt_s      = sa::f_DT_S();
    const float k_ahp     = sa::f_K_AHP();
    const float k_ref     = sa::f_K_REF();
    const float z_th      = sa::f_Z_TH();
    const float r_gain    = sa::f_R();
    const float add_ahp   = sa::f_I_TH_AHP();
    const float add_ref   = sa::f_I_REF_ADD();

    float z = g_carry[j][n];
    float i_ahp = 0.0f, i_ref = 0.0f;   // exact while no neuron has fired
    bool any_fired = false;
    float last_fired = 0.0f;

    const int cnt = min(L_C, T - t0);
    #pragma unroll 10
    for (int i = 0; i < L_C; i++) {
        if (i >= cnt) break;
        const float x = __ldcs(xp + (size_t)i * F_C);
        const float i_in  = x * cur_scale;
        const float i_net = i_in - i_ahp - i_ref;
        const float dz = fmaf(-oma, z, i_net) * inv_tau_m;
        z = fmaf(dt_s, dz, z);
        const bool fired = (z >= z_th);
        z = fired ? 0.0f : z;
        i_ahp = fmaf(i_ahp, -k_ahp, i_ahp);
        i_ref = fmaf(i_ref, -k_ref, i_ref);
        if (fired) { i_ahp += add_ahp; i_ref += add_ref; any_fired = true; }
        const float fired_f = fired ? 1.0f : 0.0f;
        __stcg(ip + (size_t)i * F_C, z * r_gain);
        __stcg(sp + (size_t)i * F_C, fired_f);
        last_fired = fired_f;
    }

    if (t0 + cnt == T) {
        // spikes[:,T,:] = fired_{T-1}
        __stcg(sp + (size_t)cnt * F_C, last_fired);
    }
    if (any_fired) g_flags[n] = 1u;  // chunk decomposition invalid for this neuron
}

// ---------------------------------------------------------------------------
// FB: exact serial recompute for flagged neurons (correctness insurance).
// No flags set -> returns immediately.
// ---------------------------------------------------------------------------
__global__ __launch_bounds__(128)
void sa_fallback(const float* __restrict__ in,
                 float* __restrict__ imem,
                 float* __restrict__ spk, int T)
{
    const int n = blockIdx.x * blockDim.x + threadIdx.x;
    if (n >= N_C) return;
    if (g_flags[n] == 0u) return;

    const int b = n >> 10;
    const int f = n & (F_C - 1);
    const float* __restrict__ xp = in + (size_t)b * T * F_C + f;
    float* __restrict__ ip = imem + (size_t)b * (T + 1) * F_C + f;
    float* __restrict__ sp = spk  + (size_t)b * (T + 1) * F_C + f;

    const float cur_scale = sa::f_CUR_SCALE();
    const float oma       = sa::f_ONE_MINUS_A();
    const float inv_tau_m = sa::f_INV_TAU_M();
    const float dt_s      = sa::f_DT_S();
    const float k_ahp     = sa::f_K_AHP();
    const float k_ref     = sa::f_K_REF();
    const float z_th      = sa::f_Z_TH();
    const float r_gain    = sa::f_R();
    const float add_ahp   = sa::f_I_TH_AHP();
    const float add_ref   = sa::f_I_REF_ADD();

    ip[0] = 0.0f;
    float z = 0.0f, i_ahp = 0.0f, i_ref = 0.0f;
    float last_fired = 0.0f;
    for (int t = 0; t < T; t++) {
        const float x = xp[(size_t)t * F_C];
        const float i_in  = x * cur_scale;
        const float i_net = i_in - i_ahp - i_ref;
        const float dz = fmaf(-oma, z, i_net) * inv_tau_m;
        z = fmaf(dt_s, dz, z);
        const bool fired = (z >= z_th);
        z = fired ? 0.0f : z;
        i_ahp = fmaf(i_ahp, -k_ahp, i_ahp);
        i_ref = fmaf(i_ref, -k_ref, i_ref);
        if (fired) { i_ahp += add_ahp; i_ref += add_ref; }
        const float fired_f = fired ? 1.0f : 0.0f;
        ip[(size_t)(t + 1) * F_C] = z * r_gain;
        sp[(size_t)t * F_C] = fired_f;
        last_fired = fired_f;
    }
    sp[(size_t)T * F_C] = last_fired;
}

// ---------------------------------------------------------------------------
extern "C" void kernel_launch(void* const* d_in, const int* in_sizes, int n_in,
                              void* d_out, int out_size)
{
    (void)n_in;
    const int T = in_sizes[0] / (B_C * F_C);       // 2000
    const int K = (T + L_C - 1) / L_C;             // 40
    const int half = out_size / 2;

    const float* in = (const float*)d_in[0];
    float* imem_out = (float*)d_out;
    float* spk_out  = (float*)d_out + half;

    // effective per-step multiplier a = 1 - dt*oma/tau_m  (double precision)
    const double a_d = 1.0 - sa::d_DT_S * 0.2 / sa::d_TAU_M;    // 0.99
    const float  aL  = (float)std::pow(a_d, (double)L_C);
    const float  a1  = (float)a_d;

    dim3 blk(128);
    dim3 grid_nk(N_C / 128, K);
    dim3 grid_n(N_C / 128);

    sa_p1_partials<<<grid_nk, blk>>>(in, T);
    sa_p2_carry  <<<grid_n,  blk>>>(imem_out, T, K, aL, a1);
    sa_p3_replay <<<grid_nk, blk>>>(in, imem_out, spk_out, T);
    sa_fallback  <<<grid_n,  blk>>>(in, imem_out, spk_out, T);
}

// round 5
// speedup vs baseline: 1.3327x; 1.3327x over previous
#include <cuda_runtime.h>
#include <cstdint>
#include <cmath>

// SA neuron forward scan — time-parallel chunked formulation, float4-vectorized.
//
// Input : input_current [B=16, T, F=1024] float32 (T=2000 here)
// Output: d_out = concat(imem_trace [B, T+1, F] f32, spikes [B, T+1, F] f32)
//
// While no neuron fires, i_ahp = i_ref = 0 identically and the membrane is a
// linear AR(1). 3-phase chunked scan (K chunks of L steps):
//   P1: per (neuron4, chunk) partial from z=0            [reads x once]
//   P2: per neuron sequential carry zc' = a^L zc + s_j   [tiny]
//   P3: per (neuron4, chunk) exact nonlinear replay from zc, write outputs,
//       flag firing neurons                               [reads x, writes out]
//   FB: serial exact recompute for flagged neurons (correct for any input;
//       no-op for this input)

namespace sa {
constexpr double d_TAU_M   = 1e-13 * 0.026 / (0.7 * 2.5e-11);
constexpr double d_DT_S    = (d_TAU_M * 1000.0 / 20.0) * 0.001;
constexpr double d_TAU_AHP = 2.5e-13 * 0.026 / (0.7 * 2e-11);
constexpr double d_TAU_REF = 2e-13 * 0.026 / (0.7 * 1.6e-9);

__device__ __host__ __forceinline__ float f_CUR_SCALE() { return 1e-12f; }
__device__ __host__ __forceinline__ float f_ONE_MINUS_A() { return 0.2f; }
__device__ __host__ __forceinline__ float f_INV_TAU_M() { return (float)(1.0 / d_TAU_M); }
__device__ __host__ __forceinline__ float f_DT_S() { return (float)d_DT_S; }
__device__ __host__ __forceinline__ float f_K_AHP() { return (float)(d_DT_S / d_TAU_AHP); }
__device__ __host__ __forceinline__ float f_K_REF() { return (float)(d_DT_S / d_TAU_REF); }
__device__ __host__ __forceinline__ float f_Z_TH() { return 2.5e-9f; }
__device__ __host__ __forceinline__ float f_R() { return 332.0f; }
__device__ __host__ __forceinline__ float f_I_TH_AHP() { return 1.66e-11f; }
__device__ __host__ __forceinline__ float f_I_REF_ADD() { return 1.6e-9f; }
} // namespace sa

constexpr int B_C = 16;
constexpr int F_C = 1024;
constexpr int N_C = B_C * F_C;          // 16384 neurons
constexpr int N4_C = N_C / 4;           // 4096 float4 lanes
constexpr int L_C = 50;                 // chunk length
constexpr int K_MAX = 128;              // supports T up to 6400

// Scratch (allocation-free rule: __device__ globals)
__device__ float    g_s[K_MAX][N_C];      // chunk partials (zero-carry result)
__device__ float    g_carry[K_MAX][N_C];  // carry-in z per chunk
__device__ unsigned g_flags[N_C];         // per-neuron "fired somewhere" flag

// ---------------------------------------------------------------------------
// P1: chunk partials, pure linear (no-fire) dynamics from z=0. float4/thread.
// grid: (N4/128, K), block 128. Lane f-quads consecutive -> 512B/warp loads.
// ---------------------------------------------------------------------------
__global__ __launch_bounds__(128)
void sa_p1_partials(const float* __restrict__ in, int T)
{
    const int n4 = blockIdx.x * blockDim.x + threadIdx.x;   // 0..N4-1
    const int j  = blockIdx.y;
    const int t0 = j * L_C;
    if (t0 >= T) return;
    const int n = n4 * 4;
    const int b = n >> 10;
    const int f = n & (F_C - 1);
    const float* __restrict__ xp = in + (size_t)b * T * F_C + (size_t)t0 * F_C + f;

    const float cs  = sa::f_CUR_SCALE();
    const float oma = sa::f_ONE_MINUS_A();
    const float itm = sa::f_INV_TAU_M();
    const float dt  = sa::f_DT_S();

    float4 z = make_float4(0.f, 0.f, 0.f, 0.f);
    const int cnt = min(L_C, T - t0);

    if (cnt == L_C) {
        #pragma unroll 10
        for (int i = 0; i < L_C; i++) {
            const float4 x = __ldcs((const float4*)(xp + (size_t)i * F_C));
            z.x = fmaf(dt, fmaf(-oma, z.x, x.x * cs) * itm, z.x);
            z.y = fmaf(dt, fmaf(-oma, z.y, x.y * cs) * itm, z.y);
            z.z = fmaf(dt, fmaf(-oma, z.z, x.z * cs) * itm, z.z);
            z.w = fmaf(dt, fmaf(-oma, z.w, x.w * cs) * itm, z.w);
        }
    } else {
        for (int i = 0; i < cnt; i++) {
            const float4 x = __ldcs((const float4*)(xp + (size_t)i * F_C));
            z.x = fmaf(dt, fmaf(-oma, z.x, x.x * cs) * itm, z.x);
            z.y = fmaf(dt, fmaf(-oma, z.y, x.y * cs) * itm, z.y);
            z.z = fmaf(dt, fmaf(-oma, z.z, x.z * cs) * itm, z.z);
            z.w = fmaf(dt, fmaf(-oma, z.w, x.w * cs) * itm, z.w);
        }
    }
    *(float4*)&g_s[j][n] = z;
}

// ---------------------------------------------------------------------------
// P2: sequential carry combine per neuron, zero flags, imem[:,0,:] = 0
// ---------------------------------------------------------------------------
__global__ __launch_bounds__(128)
void sa_p2_carry(float* __restrict__ imem, int T, int K, float aL, float a1)
{
    const int n = blockIdx.x * blockDim.x + threadIdx.x;
    if (n >= N_C) return;
    g_flags[n] = 0u;

    float zc = 0.0f;
    for (int j = 0; j < K; j++) {
        g_carry[j][n] = zc;
        const int cnt = min(L_C, T - j * L_C);
        const float aj = (cnt == L_C) ? aL : __powf(a1, (float)cnt);
        zc = fmaf(aj, zc, g_s[j][n]);
    }

    // imem_trace[:,0,:] = 0
    const int b = n >> 10;
    const int f = n & (F_C - 1);
    imem[(size_t)b * (T + 1) * F_C + f] = 0.0f;
}

// ---------------------------------------------------------------------------
// P3: exact nonlinear replay per (neuron4, chunk) from the linear carry,
//     write imem/spikes with STG.128, flag firing neurons.
// ---------------------------------------------------------------------------
__global__ __launch_bounds__(128)
void sa_p3_replay(const float* __restrict__ in,
                  float* __restrict__ imem,
                  float* __restrict__ spk, int T)
{
    const int n4 = blockIdx.x * blockDim.x + threadIdx.x;
    const int j  = blockIdx.y;
    const int t0 = j * L_C;
    if (t0 >= T) return;
    const int n = n4 * 4;
    const int b = n >> 10;
    const int f = n & (F_C - 1);

    const float* __restrict__ xp = in + (size_t)b * T * F_C + (size_t)t0 * F_C + f;
    float* __restrict__ ip = imem + (size_t)b * (T + 1) * F_C + (size_t)(t0 + 1) * F_C + f;
    float* __restrict__ sp = spk  + (size_t)b * (T + 1) * F_C + (size_t)t0 * F_C + f;

    const float cs   = sa::f_CUR_SCALE();
    const float oma  = sa::f_ONE_MINUS_A();
    const float itm  = sa::f_INV_TAU_M();
    const float dt   = sa::f_DT_S();
    const float kah  = sa::f_K_AHP();
    const float kre  = sa::f_K_REF();
    const float zth  = sa::f_Z_TH();
    const float rg   = sa::f_R();
    const float aah  = sa::f_I_TH_AHP();
    const float are  = sa::f_I_REF_ADD();

    float4 z   = *(const float4*)&g_carry[j][n];
    float4 ahp = make_float4(0.f, 0.f, 0.f, 0.f);
    float4 ref = make_float4(0.f, 0.f, 0.f, 0.f);
    unsigned fired_mask = 0u;            // bit c: component c fired somewhere
    float4 lastf = make_float4(0.f, 0.f, 0.f, 0.f);

    const int cnt = min(L_C, T - t0);

    #define SA_STEP(ZC, AC, RC, XC, FC, BIT)                                  \
        {                                                                     \
            const float i_net = fmaf(XC, cs, -(AC) - (RC));                   \
            ZC = fmaf(dt, fmaf(-oma, ZC, i_net) * itm, ZC);                   \
            const bool fd = (ZC >= zth);                                      \
            ZC = fd ? 0.0f : ZC;                                              \
            AC = fmaf(AC, -kah, AC);                                          \
            RC = fmaf(RC, -kre, RC);                                          \
            if (fd) { AC += aah; RC += are; fired_mask |= (1u << BIT); }      \
            FC = fd ? 1.0f : 0.0f;                                            \
        }

    if (cnt == L_C) {
        #pragma unroll 10
        for (int i = 0; i < L_C; i++) {
            const float4 x = __ldcs((const float4*)(xp + (size_t)i * F_C));
            float4 ff;
            SA_STEP(z.x, ahp.x, ref.x, x.x, ff.x, 0)
            SA_STEP(z.y, ahp.y, ref.y, x.y, ff.y, 1)
            SA_STEP(z.z, ahp.z, ref.z, x.z, ff.z, 2)
            SA_STEP(z.w, ahp.w, ref.w, x.w, ff.w, 3)
            const float4 im = make_float4(z.x * rg, z.y * rg, z.z * rg, z.w * rg);
            __stcs((float4*)(ip + (size_t)i * F_C), im);
            __stcs((float4*)(sp + (size_t)i * F_C), ff);
            lastf = ff;
        }
    } else {
        for (int i = 0; i < cnt; i++) {
            const float4 x = __ldcs((const float4*)(xp + (size_t)i * F_C));
            float4 ff;
            SA_STEP(z.x, ahp.x, ref.x, x.x, ff.x, 0)
            SA_STEP(z.y, ahp.y, ref.y, x.y, ff.y, 1)
            SA_STEP(z.z, ahp.z, ref.z, x.z, ff.z, 2)
            SA_STEP(z.w, ahp.w, ref.w, x.w, ff.w, 3)
            const float4 im = make_float4(z.x * rg, z.y * rg, z.z * rg, z.w * rg);
            __stcs((float4*)(ip + (size_t)i * F_C), im);
            __stcs((float4*)(sp + (size_t)i * F_C), ff);
            lastf = ff;
        }
    }
    #undef SA_STEP

    if (t0 + cnt == T) {
        // spikes[:,T,:] = fired_{T-1}
        __stcs((float4*)(sp + (size_t)cnt * F_C), lastf);
    }
    if (fired_mask) {   // rare path: mark each fired neuron for exact redo
        if (fired_mask & 1u) g_flags[n + 0] = 1u;
        if (fired_mask & 2u) g_flags[n + 1] = 1u;
        if (fired_mask & 4u) g_flags[n + 2] = 1u;
        if (fired_mask & 8u) g_flags[n + 3] = 1u;
    }
}

// ---------------------------------------------------------------------------
// FB: exact serial recompute for flagged neurons (correctness insurance).
// ---------------------------------------------------------------------------
__global__ __launch_bounds__(128)
void sa_fallback(const float* __restrict__ in,
                 float* __restrict__ imem,
                 float* __restrict__ spk, int T)
{
    const int n = blockIdx.x * blockDim.x + threadIdx.x;
    if (n >= N_C) return;
    if (g_flags[n] == 0u) return;

    const int b = n >> 10;
    const int f = n & (F_C - 1);
    const float* __restrict__ xp = in + (size_t)b * T * F_C + f;
    float* __restrict__ ip = imem + (size_t)b * (T + 1) * F_C + f;
    float* __restrict__ sp = spk  + (size_t)b * (T + 1) * F_C + f;

    const float cs  = sa::f_CUR_SCALE();
    const float oma = sa::f_ONE_MINUS_A();
    const float itm = sa::f_INV_TAU_M();
    const float dt  = sa::f_DT_S();
    const float kah = sa::f_K_AHP();
    const float kre = sa::f_K_REF();
    const float zth = sa::f_Z_TH();
    const float rg  = sa::f_R();
    const float aah = sa::f_I_TH_AHP();
    const float are = sa::f_I_REF_ADD();

    ip[0] = 0.0f;
    float z = 0.0f, ahp = 0.0f, ref = 0.0f;
    float lastf = 0.0f;
    for (int t = 0; t < T; t++) {
        const float x = xp[(size_t)t * F_C];
        const float i_net = fmaf(x, cs, -ahp - ref);
        z = fmaf(dt, fmaf(-oma, z, i_net) * itm, z);
        const bool fd = (z >= zth);
        z = fd ? 0.0f : z;
        ahp = fmaf(ahp, -kah, ahp);
        ref = fmaf(ref, -kre, ref);
        if (fd) { ahp += aah; ref += are; }
        const float ff = fd ? 1.0f : 0.0f;
        ip[(size_t)(t + 1) * F_C] = z * rg;
        sp[(size_t)t * F_C] = ff;
        lastf = ff;
    }
    sp[(size_t)T * F_C] = lastf;
}

// ---------------------------------------------------------------------------
extern "C" void kernel_launch(void* const* d_in, const int* in_sizes, int n_in,
                              void* d_out, int out_size)
{
    (void)n_in;
    const int T = in_sizes[0] / (B_C * F_C);       // 2000
    const int K = (T + L_C - 1) / L_C;             // 40
    const int half = out_size / 2;

    const float* in = (const float*)d_in[0];
    float* imem_out = (float*)d_out;
    float* spk_out  = (float*)d_out + half;

    // effective per-step multiplier a = 1 - dt*oma/tau_m  (double precision)
    const double a_d = 1.0 - sa::d_DT_S * 0.2 / sa::d_TAU_M;    // 0.99
    const float  aL  = (float)std::pow(a_d, (double)L_C);
    const float  a1  = (float)a_d;

    dim3 blk(128);
    dim3 grid_nk4(N4_C / 128, K);    // (32, K)
    dim3 grid_n(N_C / 128);          // 128

    sa_p1_partials<<<grid_nk4, blk>>>(in, T);
    sa_p2_carry  <<<grid_n,   blk>>>(imem_out, T, K, aL, a1);
    sa_p3_replay <<<grid_nk4, blk>>>(in, imem_out, spk_out, T);
    sa_fallback  <<<grid_n,   blk>>>(in, imem_out, spk_out, T);
}